// round 1
// baseline (speedup 1.0000x reference)
#include <cuda_runtime.h>

// Problem constants (RFInterDAS): rf[8,128,2048], d_tx[8,384,192], d_rx/apod[128,384,192]
#define N_ANG   8
#define N_EL    128
#define N_SAMP  2048
#define NPIX    (384*192)        // 73728
#define TPB     256
#define PPT     4                // pixels per thread
#define TILE    (TPB*PPT)        // 1024
#define NTILES  (NPIX/TILE)      // 72
#define EG      2                // element groups (grid.y)
#define EPG     (N_EL/EG)        // 64 elements per CTA

__global__ void zero_out_kernel(float* __restrict__ out, int n) {
    int i = blockIdx.x * blockDim.x + threadIdx.x;
    if (i < n) out[i] = 0.0f;
}

extern __shared__ float srf[];   // 8 rows x 2048 floats = 64 KB

__global__ __launch_bounds__(TPB)
void das_kernel(const float* __restrict__ rf,
                const float* __restrict__ t0,
                const float* __restrict__ d_tx,
                const float* __restrict__ d_rx,
                const float* __restrict__ fs_p,
                const float* __restrict__ c0_p,
                const float* __restrict__ apod,
                float* __restrict__ out)
{
    const int tile = blockIdx.x;
    const int eg   = blockIdx.y;
    const int tid  = threadIdx.x;

    const float fs    = *fs_p;
    const float c0    = *c0_p;
    const float scale = fs / c0;

    // Per-pixel, per-angle tx delay (in samples) held in registers.
    int   pix[PPT];
    float txs[PPT][N_ANG];
    float acc[PPT][N_ANG];
    float t0fs[N_ANG];
#pragma unroll
    for (int a = 0; a < N_ANG; a++) t0fs[a] = t0[a] * fs;
#pragma unroll
    for (int k = 0; k < PPT; k++) {
        pix[k] = tile * TILE + k * TPB + tid;
#pragma unroll
        for (int a = 0; a < N_ANG; a++) {
            txs[k][a] = fmaf(d_tx[a * NPIX + pix[k]], scale, t0fs[a]);
            acc[k][a] = 0.0f;
        }
    }

    const int e0 = eg * EPG;
    for (int e = e0; e < e0 + EPG; e++) {
        __syncthreads();  // previous iteration's reads done before overwrite
        // Stage rf rows for all 8 angles, element e: 4096 float4 total.
#pragma unroll
        for (int j = 0; j < (N_ANG * N_SAMP / 4) / TPB; j++) {  // 16 iters
            int q  = j * TPB + tid;          // float4 index in [0, 4096)
            int a  = q >> 9;                 // q / 512
            int c4 = q & 511;
            const float4* src =
                reinterpret_cast<const float4*>(rf + ((size_t)(a * N_EL + e)) * N_SAMP);
            reinterpret_cast<float4*>(srf)[q] = src[c4];
        }
        __syncthreads();

#pragma unroll
        for (int k = 0; k < PPT; k++) {
            const float rx = d_rx[(size_t)e * NPIX + pix[k]] * scale;
            const float ap = apod[(size_t)e * NPIX + pix[k]];
#pragma unroll
            for (int a = 0; a < N_ANG; a++) {
                float s = txs[k][a] + rx;
                s = fminf(fmaxf(s, 0.0f), 2046.999f);
                int   i = (int)s;            // s >= 0 -> trunc == floor
                float f = s - (float)i;
                const float* row = srf + a * N_SAMP + i;
                float lo = row[0];
                float hi = row[1];
                float sm = fmaf(f, hi - lo, lo);
                acc[k][a] = fmaf(sm, ap, acc[k][a]);
            }
        }
    }

    // Exactly EG(=2) commutative float adds per output element: deterministic.
#pragma unroll
    for (int k = 0; k < PPT; k++)
#pragma unroll
        for (int a = 0; a < N_ANG; a++)
            atomicAdd(&out[a * NPIX + pix[k]], acc[k][a]);
}

extern "C" void kernel_launch(void* const* d_in, const int* in_sizes, int n_in,
                              void* d_out, int out_size)
{
    const float* rf   = (const float*)d_in[0];
    const float* t0   = (const float*)d_in[1];
    const float* d_tx = (const float*)d_in[2];
    const float* d_rx = (const float*)d_in[3];
    const float* fs   = (const float*)d_in[4];
    const float* c0   = (const float*)d_in[5];
    const float* apod = (const float*)d_in[6];
    float* out = (float*)d_out;

    cudaFuncSetAttribute(das_kernel,
                         cudaFuncAttributeMaxDynamicSharedMemorySize,
                         N_ANG * N_SAMP * (int)sizeof(float));

    zero_out_kernel<<<(out_size + TPB - 1) / TPB, TPB>>>(out, out_size);

    dim3 grid(NTILES, EG);
    das_kernel<<<grid, TPB, N_ANG * N_SAMP * sizeof(float)>>>(
        rf, t0, d_tx, d_rx, fs, c0, apod, out);
}

// round 2
// speedup vs baseline: 1.3909x; 1.3909x over previous
#include <cuda_runtime.h>
#include <cstdint>

// Problem constants (RFInterDAS): rf[8,128,2048], d_tx[8,384,192], d_rx/apod[128,384,192]
#define N_ANG   8
#define N_EL    128
#define N_SAMP  2048
#define NPIX    (384*192)        // 73728
#define TPB     256
#define PPT     4                // pixels per thread
#define TILE    (TPB*PPT)        // 1024
#define NTILES  (NPIX/TILE)      // 72
#define EG      4                // element groups (grid.y)
#define EPG     (N_EL/EG)        // 32 elements per CTA

__global__ void zero_out_kernel(float* __restrict__ out, int n) {
    int i = blockIdx.x * blockDim.x + threadIdx.x;
    if (i < n) out[i] = 0.0f;
}

extern __shared__ float srf[];   // 8 rows x 2048 floats = 64 KB

__device__ __forceinline__ void cp_async16(uint32_t dst_smem, const void* src) {
    asm volatile("cp.async.cg.shared.global [%0], [%1], 16;\n"
                 :: "r"(dst_smem), "l"(src) : "memory");
}
__device__ __forceinline__ void cp_async_commit() {
    asm volatile("cp.async.commit_group;\n" ::: "memory");
}
__device__ __forceinline__ void cp_async_wait0() {
    asm volatile("cp.async.wait_group 0;\n" ::: "memory");
}

__global__ __launch_bounds__(TPB, 2)
void das_kernel(const float* __restrict__ rf,
                const float* __restrict__ t0,
                const float* __restrict__ d_tx,
                const float* __restrict__ d_rx,
                const float* __restrict__ fs_p,
                const float* __restrict__ c0_p,
                const float* __restrict__ apod,
                float* __restrict__ out)
{
    const int tile = blockIdx.x;
    const int eg   = blockIdx.y;
    const int tid  = threadIdx.x;

    const float fs    = *fs_p;
    const float c0    = *c0_p;
    const float scale = fs / c0;

    const uint32_t srf_s = (uint32_t)__cvta_generic_to_shared(srf);

    // Per-pixel, per-angle tx delay (in samples) held in registers.
    int   pix[PPT];
    float txs[PPT][N_ANG];
    float acc[PPT][N_ANG];
    float t0fs[N_ANG];
#pragma unroll
    for (int a = 0; a < N_ANG; a++) t0fs[a] = t0[a] * fs;
#pragma unroll
    for (int k = 0; k < PPT; k++) {
        pix[k] = tile * TILE + k * TPB + tid;
#pragma unroll
        for (int a = 0; a < N_ANG; a++) {
            txs[k][a] = fmaf(d_tx[a * NPIX + pix[k]], scale, t0fs[a]);
            acc[k][a] = 0.0f;
        }
    }

    const int e0 = eg * EPG;
    for (int e = e0; e < e0 + EPG; e++) {
        __syncthreads();  // previous iteration's reads done before overwrite
        // Stage rf rows for all 8 angles, element e: 4096 x 16B via cp.async.
#pragma unroll
        for (int j = 0; j < (N_ANG * N_SAMP / 4) / TPB; j++) {  // 16 iters
            int q  = j * TPB + tid;          // float4 index in [0, 4096)
            int a  = q >> 9;                 // q / 512
            int c4 = q & 511;
            const float4* src =
                reinterpret_cast<const float4*>(rf + ((size_t)(a * N_EL + e)) * N_SAMP) + c4;
            cp_async16(srf_s + (uint32_t)q * 16u, src);
        }
        cp_async_commit();

        // Overlap: pull the per-element streaming operands while copies fly.
        float rx[PPT], ap[PPT];
#pragma unroll
        for (int k = 0; k < PPT; k++) {
            rx[k] = d_rx[(size_t)e * NPIX + pix[k]] * scale;
            ap[k] = apod[(size_t)e * NPIX + pix[k]];
        }

        cp_async_wait0();
        __syncthreads();

#pragma unroll
        for (int k = 0; k < PPT; k++) {
#pragma unroll
            for (int a = 0; a < N_ANG; a++) {
                float s = txs[k][a] + rx[k];
                s = fminf(fmaxf(s, 0.0f), 2046.999f);
                int   i = (int)s;            // s >= 0 -> trunc == floor
                float f = s - (float)i;
                const float* row = srf + a * N_SAMP + i;
                float lo = row[0];
                float hi = row[1];
                float sm = fmaf(f, hi - lo, lo);
                acc[k][a] = fmaf(sm, ap[k], acc[k][a]);
            }
        }
    }

    // Exactly EG(=4) commutative float adds per output element.
#pragma unroll
    for (int k = 0; k < PPT; k++)
#pragma unroll
        for (int a = 0; a < N_ANG; a++)
            atomicAdd(&out[a * NPIX + pix[k]], acc[k][a]);
}

extern "C" void kernel_launch(void* const* d_in, const int* in_sizes, int n_in,
                              void* d_out, int out_size)
{
    const float* rf   = (const float*)d_in[0];
    const float* t0   = (const float*)d_in[1];
    const float* d_tx = (const float*)d_in[2];
    const float* d_rx = (const float*)d_in[3];
    const float* fs   = (const float*)d_in[4];
    const float* c0   = (const float*)d_in[5];
    const float* apod = (const float*)d_in[6];
    float* out = (float*)d_out;

    cudaFuncSetAttribute(das_kernel,
                         cudaFuncAttributeMaxDynamicSharedMemorySize,
                         N_ANG * N_SAMP * (int)sizeof(float));

    zero_out_kernel<<<(out_size + TPB - 1) / TPB, TPB>>>(out, out_size);

    dim3 grid(NTILES, EG);
    das_kernel<<<grid, TPB, N_ANG * N_SAMP * sizeof(float)>>>(
        rf, t0, d_tx, d_rx, fs, c0, apod, out);
}